// round 4
// baseline (speedup 1.0000x reference)
#include <cuda_runtime.h>
#include <cstring>

#define BB 128
#define TT 512
#define II 128
#define HH 256

__device__ float g_xp[(size_t)BB * TT * HH];   // [B][T][H] fp32, 64 MB scratch

// Packed fp32x2 FMA (sm_103a): two fp32 FMA lanes per issue.
__device__ __forceinline__ float2 ffma2(float2 a, float2 b, float2 c) {
    unsigned long long ua, ub, uc, ud;
    memcpy(&ua, &a, 8); memcpy(&ub, &b, 8); memcpy(&uc, &c, 8);
    asm("fma.rn.f32x2 %0, %1, %2, %3;" : "=l"(ud) : "l"(ua), "l"(ub), "l"(uc));
    float2 d; memcpy(&d, &ud, 8); return d;
}

// ---------------------------------------------------------------------------
// Phase 1: xp[r,h] = x[r,:] . W_ih[h,:] + (b_ih[h] + b_hh[h])
// 128 CTAs x 256 threads; W_ih row per thread in regs; x double-buffered.
// ---------------------------------------------------------------------------
__global__ void __launch_bounds__(256, 1)
rnn_xproj(const float* __restrict__ x,
          const float* __restrict__ W_ih,
          const float* __restrict__ b_ih,
          const float* __restrict__ b_hh) {
    __shared__ float xs[2][8 * II];

    const int h = threadIdx.x;

    const float4* Wi4 = (const float4*)W_ih;
    float4 wreg[32];
#pragma unroll
    for (int q = 0; q < 32; q++) wreg[q] = Wi4[h * 32 + q];

    const float bias = b_ih[h] + b_hh[h];
    const size_t base_row = (size_t)blockIdx.x * 512;

    ((float4*)xs[0])[h] = ((const float4*)(x + base_row * II))[h];
    __syncthreads();

    for (int tile = 0; tile < 64; tile++) {
        const int cur = tile & 1;
        if (tile < 63) {
            ((float4*)xs[cur ^ 1])[h] =
                ((const float4*)(x + (base_row + (size_t)(tile + 1) * 8) * II))[h];
        }

        const size_t r0 = base_row + (size_t)tile * 8;
#pragma unroll
        for (int r = 0; r < 8; r += 2) {
            const float4* x0 = (const float4*)(xs[cur] + r * II);
            const float4* x1 = (const float4*)(xs[cur] + (r + 1) * II);
            float2 a0 = make_float2(bias, 0.0f), a1 = make_float2(0.0f, 0.0f);
            float2 c0 = make_float2(bias, 0.0f), c1 = make_float2(0.0f, 0.0f);
#pragma unroll
            for (int q = 0; q < 32; q++) {
                float4 xv = x0[q], yv = x1[q];
                float2 wlo = make_float2(wreg[q].x, wreg[q].y);
                float2 whi = make_float2(wreg[q].z, wreg[q].w);
                a0 = ffma2(make_float2(xv.x, xv.y), wlo, a0);
                a1 = ffma2(make_float2(xv.z, xv.w), whi, a1);
                c0 = ffma2(make_float2(yv.x, yv.y), wlo, c0);
                c1 = ffma2(make_float2(yv.z, yv.w), whi, c1);
            }
            g_xp[(r0 + r) * HH + h]     = (a0.x + a0.y) + (a1.x + a1.y);
            g_xp[(r0 + r + 1) * HH + h] = (c0.x + c0.y) + (c1.x + c1.y);
        }
        __syncthreads();
    }
}

// ---------------------------------------------------------------------------
// Phase 2 + 3: recurrent scan. 128 CTAs x 512 threads.
// Thread (j = tid&255, half = tid>>8) computes the half-dot of feature j
// over k in [half*128, half*128+128). W_hh slice: 24 float4 = 96 regs/thread
// -> 128-reg cap leaves headroom so ptxas can pipeline the broadcast h-loads.
// half-1 stores its partial to SMEM; half-0 combines, tanh, publishes h
// (double-buffered). 2 barriers/step, 16 warps/CTA.
// ---------------------------------------------------------------------------
__global__ void __launch_bounds__(512, 1)
rnn_scan(const float* __restrict__ W_hh,
         const float* __restrict__ W_fc,
         const float* __restrict__ b_fc,
         float* __restrict__ out) {
    __shared__ float hA[HH];
    __shared__ float hB[HH];
    __shared__ float ps[HH];     // half-1 partial sums
    __shared__ float red[8];

    const int tid  = threadIdx.x;
    const int j    = tid & 255;
    const int half = tid >> 8;
    const int b    = blockIdx.x;

    // W_hh[j][half*128 : half*128+128) -> 24... (32 float4? 128 floats = 32 float4)
    const float4* W4 = (const float4*)W_hh;   // row j = W4[j*64 .. j*64+63]
    float4 wreg[32];
#pragma unroll
    for (int q = 0; q < 32; q++) wreg[q] = W4[j * 64 + half * 32 + q];

    if (half == 0) hA[j] = 0.0f;
    __syncthreads();

    const float* xp = g_xp + (size_t)b * TT * HH + j;
    float* hcur = hA;
    float* hnxt = hB;
    float hn = 0.0f;

    for (int t = 0; t < TT; t++) {
        float xpv = 0.0f;
        if (half == 0) xpv = xp[(size_t)t * HH];   // early issue

        // half-dot: h[half*128 .. +128) . wreg  (broadcast LDS, pipelined)
        const float4* h4p = (const float4*)(hcur + half * 128);
        float2 a0 = make_float2(0.0f, 0.0f), a1 = a0, a2 = a0, a3 = a0;
#pragma unroll
        for (int q = 0; q < 32; q += 2) {
            float4 h4 = h4p[q];
            float4 g4 = h4p[q + 1];
            a0 = ffma2(make_float2(h4.x, h4.y), make_float2(wreg[q].x, wreg[q].y), a0);
            a1 = ffma2(make_float2(h4.z, h4.w), make_float2(wreg[q].z, wreg[q].w), a1);
            a2 = ffma2(make_float2(g4.x, g4.y), make_float2(wreg[q+1].x, wreg[q+1].y), a2);
            a3 = ffma2(make_float2(g4.z, g4.w), make_float2(wreg[q+1].z, wreg[q+1].w), a3);
        }
        const float dot = ((a0.x + a0.y) + (a1.x + a1.y)) +
                          ((a2.x + a2.y) + (a3.x + a3.y));

        if (half == 1) ps[j] = dot;
        __syncthreads();                       // partials visible; hcur reads done

        if (half == 0) {
            hn = tanhf(xpv + dot + ps[j]);
            hnxt[j] = hn;
        }
        __syncthreads();                       // new h visible

        float* tmp = hcur; hcur = hnxt; hnxt = tmp;
    }

    // Phase 3: out[b] = sigmoid(h . W_fc + b_fc)  (first 256 threads hold hn)
    if (half == 0) {
        float v = hn * W_fc[j];
#pragma unroll
        for (int o = 16; o > 0; o >>= 1) v += __shfl_down_sync(0xffffffffu, v, o);
        if ((j & 31) == 0) red[j >> 5] = v;
    }
    __syncthreads();
    if (tid == 0) {
        float s = b_fc[0];
#pragma unroll
        for (int w = 0; w < 8; w++) s += red[w];
        out[b] = 1.0f / (1.0f + expf(-s));
    }
}

// ---------------------------------------------------------------------------

extern "C" void kernel_launch(void* const* d_in, const int* in_sizes, int n_in,
                              void* d_out, int out_size) {
    const float* x    = (const float*)d_in[0];
    const float* W_ih = (const float*)d_in[1];
    const float* W_hh = (const float*)d_in[2];
    const float* b_ih = (const float*)d_in[3];
    const float* b_hh = (const float*)d_in[4];
    const float* W_fc = (const float*)d_in[5];
    const float* b_fc = (const float*)d_in[6];
    float* out = (float*)d_out;

    rnn_xproj<<<128, 256>>>(x, W_ih, b_ih, b_hh);
    rnn_scan<<<BB, 512>>>(W_hh, W_fc, b_fc, out);
}

// round 5
// speedup vs baseline: 1.4545x; 1.4545x over previous
#include <cuda_runtime.h>
#include <cstring>

#define BB 128
#define TT 512
#define II 128
#define HH 256

__device__ float g_xp[(size_t)BB * TT * HH];   // [B][T][H] fp32 scratch (fits L2)

// Packed fp32x2 FMA (sm_103a): two fp32 FMA lanes per issue.
__device__ __forceinline__ float2 ffma2(float2 a, float2 b, float2 c) {
    unsigned long long ua, ub, uc, ud;
    memcpy(&ua, &a, 8); memcpy(&ub, &b, 8); memcpy(&uc, &c, 8);
    asm("fma.rn.f32x2 %0, %1, %2, %3;" : "=l"(ud) : "l"(ua), "l"(ub), "l"(uc));
    float2 d; memcpy(&d, &ud, 8); return d;
}

// ---------------------------------------------------------------------------
// Phase 1: xp[r,h] = x[r,:] . W_ih[h,:] + (b_ih[h] + b_hh[h])
// 128 CTAs x 256 threads; W_ih row per thread in regs; x double-buffered.
// ---------------------------------------------------------------------------
__global__ void __launch_bounds__(256, 1)
rnn_xproj(const float* __restrict__ x,
          const float* __restrict__ W_ih,
          const float* __restrict__ b_ih,
          const float* __restrict__ b_hh) {
    __shared__ float xs[2][8 * II];

    const int h = threadIdx.x;

    const float4* Wi4 = (const float4*)W_ih;
    float4 wreg[32];
#pragma unroll
    for (int q = 0; q < 32; q++) wreg[q] = Wi4[h * 32 + q];

    const float bias = b_ih[h] + b_hh[h];
    const size_t base_row = (size_t)blockIdx.x * 512;

    ((float4*)xs[0])[h] = ((const float4*)(x + base_row * II))[h];
    __syncthreads();

    for (int tile = 0; tile < 64; tile++) {
        const int cur = tile & 1;
        if (tile < 63) {
            ((float4*)xs[cur ^ 1])[h] =
                ((const float4*)(x + (base_row + (size_t)(tile + 1) * 8) * II))[h];
        }

        const size_t r0 = base_row + (size_t)tile * 8;
#pragma unroll
        for (int r = 0; r < 8; r += 2) {
            const float4* x0 = (const float4*)(xs[cur] + r * II);
            const float4* x1 = (const float4*)(xs[cur] + (r + 1) * II);
            float2 a0 = make_float2(bias, 0.0f), a1 = make_float2(0.0f, 0.0f);
            float2 c0 = make_float2(bias, 0.0f), c1 = make_float2(0.0f, 0.0f);
#pragma unroll
            for (int q = 0; q < 32; q++) {
                float4 xv = x0[q], yv = x1[q];
                float2 wlo = make_float2(wreg[q].x, wreg[q].y);
                float2 whi = make_float2(wreg[q].z, wreg[q].w);
                a0 = ffma2(make_float2(xv.x, xv.y), wlo, a0);
                a1 = ffma2(make_float2(xv.z, xv.w), whi, a1);
                c0 = ffma2(make_float2(yv.x, yv.y), wlo, c0);
                c1 = ffma2(make_float2(yv.z, yv.w), whi, c1);
            }
            g_xp[(r0 + r) * HH + h]     = (a0.x + a0.y) + (a1.x + a1.y);
            g_xp[(r0 + r + 1) * HH + h] = (c0.x + c0.y) + (c1.x + c1.y);
        }
        __syncthreads();
    }
}

// ---------------------------------------------------------------------------
// Phase 2 + 3: recurrent scan. 128 CTAs x 512 threads (16 warps, 4/SMSP).
// Thread (j = tid&255, half = tid>>8) computes the half-dot of feature j over
// k in [half*128, half*128+128):
//   - k-floats [0,88)  of the slice: 22 float4 in REGISTERS (88 regs; ~35
//     regs of headroom under the 128-reg cap -> LDS loads can pipeline)
//   - k-floats [88,128): 10 float4 from SMEM, layout [half*10+q][j] (the
//     32 lanes of a warp read consecutive j -> conflict-free)
// half-1 writes its partial to SMEM; half-0 combines + tanh + publishes h
// (double-buffered). 2 barriers/step.
// ---------------------------------------------------------------------------
#define NREG 22          // float4s of W in registers per thread
#define NTAIL 10         // float4s of W in SMEM per thread (NREG+NTAIL == 32)

__global__ void __launch_bounds__(512, 1)
rnn_scan(const float* __restrict__ W_hh,
         const float* __restrict__ W_fc,
         const float* __restrict__ b_fc,
         float* __restrict__ out) {
    extern __shared__ float sm[];
    float4* wt4 = (float4*)sm;                       // [2*NTAIL][256] f4 = 80 KB
    float*  hA  = sm + 2 * NTAIL * 256 * 4;
    float*  hB  = hA + HH;
    float*  ps  = hB + HH;
    float*  red = ps + HH;

    const int tid  = threadIdx.x;
    const int j    = tid & 255;
    const int half = tid >> 8;
    const int b    = blockIdx.x;

    const float4* W4 = (const float4*)W_hh;          // row j = W4[j*64 .. +63]
    const int wbase = j * 64 + half * 32;

    float4 wreg[NREG];
#pragma unroll
    for (int q = 0; q < NREG; q++) wreg[q] = W4[wbase + q];

    // SMEM tail fill: wt4[(half*NTAIL + q)*256 + j] = W[j][half*128 + (NREG+q)*4 ..]
#pragma unroll
    for (int q = 0; q < NTAIL; q++)
        wt4[(half * NTAIL + q) * 256 + j] = W4[wbase + NREG + q];

    if (tid < HH) hA[tid] = 0.0f;
    __syncthreads();

    const float* xp = g_xp + (size_t)b * TT * HH + j;
    const float4* wt = wt4 + half * NTAIL * 256 + j;   // wt[q*256]

    float* hcur = hA;
    float* hnxt = hB;
    float hn = 0.0f;

    for (int t = 0; t < TT; t++) {
        float xpv = 0.0f;
        if (half == 0) xpv = xp[(size_t)t * HH];       // L2-hit, consumed late

        const float4* h4p = (const float4*)(hcur + half * 128);
        float2 a0 = make_float2(0.0f, 0.0f), a1 = a0, a2 = a0, a3 = a0;

        // SMEM W-tail first: its latency overlaps the register-W FMA stream
#pragma unroll
        for (int q = 0; q < NTAIL; q++) {
            float4 h4 = h4p[NREG + q];
            float4 w4 = wt[q * 256];
            if (q & 1) {
                a2 = ffma2(make_float2(h4.x, h4.y), make_float2(w4.x, w4.y), a2);
                a3 = ffma2(make_float2(h4.z, h4.w), make_float2(w4.z, w4.w), a3);
            } else {
                a0 = ffma2(make_float2(h4.x, h4.y), make_float2(w4.x, w4.y), a0);
                a1 = ffma2(make_float2(h4.z, h4.w), make_float2(w4.z, w4.w), a1);
            }
        }
#pragma unroll
        for (int q = 0; q < NREG; q++) {
            float4 h4 = h4p[q];
            if (q & 1) {
                a2 = ffma2(make_float2(h4.x, h4.y), make_float2(wreg[q].x, wreg[q].y), a2);
                a3 = ffma2(make_float2(h4.z, h4.w), make_float2(wreg[q].z, wreg[q].w), a3);
            } else {
                a0 = ffma2(make_float2(h4.x, h4.y), make_float2(wreg[q].x, wreg[q].y), a0);
                a1 = ffma2(make_float2(h4.z, h4.w), make_float2(wreg[q].z, wreg[q].w), a1);
            }
        }

        const float dot = ((a0.x + a0.y) + (a1.x + a1.y)) +
                          ((a2.x + a2.y) + (a3.x + a3.y));

        if (half == 1) ps[j] = dot;
        __syncthreads();                // partials visible; hcur reads done

        if (half == 0) {
            hn = tanhf(xpv + dot + ps[j]);
            hnxt[j] = hn;
        }
        __syncthreads();                // new h visible

        float* tmp = hcur; hcur = hnxt; hnxt = tmp;
    }

    // Phase 3: out[b] = sigmoid(h . W_fc + b_fc)
    if (half == 0) {
        float v = hn * W_fc[j];
#pragma unroll
        for (int o = 16; o > 0; o >>= 1) v += __shfl_down_sync(0xffffffffu, v, o);
        if ((j & 31) == 0) red[j >> 5] = v;
    }
    __syncthreads();
    if (tid == 0) {
        float s = b_fc[0];
#pragma unroll
        for (int w = 0; w < 8; w++) s += red[w];
        out[b] = 1.0f / (1.0f + expf(-s));
    }
}

// ---------------------------------------------------------------------------

extern "C" void kernel_launch(void* const* d_in, const int* in_sizes, int n_in,
                              void* d_out, int out_size) {
    const float* x    = (const float*)d_in[0];
    const float* W_ih = (const float*)d_in[1];
    const float* W_hh = (const float*)d_in[2];
    const float* b_ih = (const float*)d_in[3];
    const float* b_hh = (const float*)d_in[4];
    const float* W_fc = (const float*)d_in[5];
    const float* b_fc = (const float*)d_in[6];
    float* out = (float*)d_out;

    const int smem_b = (2 * NTAIL * 256 * 4 + 3 * HH + 32) * (int)sizeof(float); // ~85 KB
    cudaFuncSetAttribute(rnn_scan, cudaFuncAttributeMaxDynamicSharedMemorySize, smem_b);

    rnn_xproj<<<128, 256>>>(x, W_ih, b_ih, b_hh);
    rnn_scan<<<BB, 512, smem_b>>>(W_hh, W_fc, b_fc, out);
}